// round 3
// baseline (speedup 1.0000x reference)
#include <cuda_runtime.h>

#define B_   256
#define T_   512
#define DIN  128
#define H_   512
#define DOUT 64

#define CLUSTER_SZ 8
#define BC         16                 // batches per cluster
#define COLS_CTA   (H_ / CLUSTER_SZ)  // 64 hidden cols per CTA
#define WSTRIDE2   514                // float2 row stride for Wrec smem (512 + 2 pad)

// Scratch (allocation-free rule: __device__ globals)
__device__ float g_xproj[(size_t)B_ * T_ * H_];  // [b][t][h] = inputs@Win + brec
__device__ float g_hall [(size_t)B_ * T_ * H_];  // [b][t][h] = h_t for all t
__device__ float g_h    [2 * B_ * H_];           // ping-pong h exchange buffer

// Packed fp32x2 FMA (Blackwell FFMA2): 2x fp32 FMA throughput vs FFMA-3reg.
union F2U { float2 f; unsigned long long u; };
__device__ __forceinline__ float2 ffma2(float2 a, float2 b, float2 c) {
    F2U A, Bv, C, D;
    A.f = a; Bv.f = b; C.f = c;
    asm("fma.rn.f32x2 %0, %1, %2, %3;" : "=l"(D.u) : "l"(A.u), "l"(Bv.u), "l"(C.u));
    return D.f;
}

// ---------------------------------------------------------------------------
// Kernel A: xproj[b][t][h] = inputs[b][t][:] @ Win[:,h] + brec[h]
// 16 rows x 512 cols per block; thread = 1 col-pair x 16 rows.
// ---------------------------------------------------------------------------
__global__ void __launch_bounds__(256) rnn_xproj(
    const float* __restrict__ inputs,
    const float* __restrict__ Win,
    const float* __restrict__ brec)
{
    __shared__ __align__(16) float2 x_dup[16][DIN];  // {x,x} duplicated, 16KB
    const int tid = threadIdx.x;
    const size_t r0 = (size_t)blockIdx.x * 16;  // row = b*T + t

    for (int i = tid; i < 16 * DIN; i += 256) {
        int r = i >> 7, k = i & (DIN - 1);
        float v = inputs[(r0 + r) * DIN + k];
        x_dup[r][k] = make_float2(v, v);
    }
    __syncthreads();

    const float2* __restrict__ W2 = reinterpret_cast<const float2*>(Win);  // [k][256]
    float2 acc[16];
#pragma unroll
    for (int r = 0; r < 16; r++) acc[r] = make_float2(0.f, 0.f);

#pragma unroll 2
    for (int k = 0; k < DIN; k += 2) {
        float2 w0 = W2[(size_t)k * (H_ / 2) + tid];
        float2 w1 = W2[(size_t)(k + 1) * (H_ / 2) + tid];
#pragma unroll
        for (int r = 0; r < 16; r++) {
            float4 hx = *reinterpret_cast<const float4*>(&x_dup[r][k]);
            acc[r] = ffma2(make_float2(hx.x, hx.y), w0, acc[r]);
            acc[r] = ffma2(make_float2(hx.z, hx.w), w1, acc[r]);
        }
    }

    float2 bb = reinterpret_cast<const float2*>(brec)[tid];
    float2* __restrict__ out2 = reinterpret_cast<float2*>(g_xproj);
#pragma unroll
    for (int r = 0; r < 16; r++)
        out2[(r0 + r) * (H_ / 2) + tid] = make_float2(acc[r].x + bb.x, acc[r].y + bb.y);
}

// ---------------------------------------------------------------------------
// Kernel B: recurrence, H-partitioned across an 8-CTA cluster.
// Each CTA: Wrec slice [512 k][64 cols] resident in SMEM; 16 batch rows.
// Thread = (col-pair cp = tid&31, k-chunk kc = tid>>5, 64 k each).
// Per step: partial GEMM (Wrec from SMEM, h broadcast from SMEM),
// cross-warp reduction over k-chunks, tanh, publish h slice to L2 ping-pong
// buffer, barrier.cluster (release/acquire), rebuild duplicated h SMEM.
// ---------------------------------------------------------------------------
extern __shared__ __align__(16) unsigned char smem_raw[];

__global__ void __launch_bounds__(256, 1) __cluster_dims__(CLUSTER_SZ, 1, 1)
rnn_recurrent(const float* __restrict__ Wrec, const float* __restrict__ h0)
{
    float2* wrec_s = reinterpret_cast<float2*>(smem_raw);            // [32][514]
    float2* h_dup  = reinterpret_cast<float2*>(smem_raw + 131584);   // [16][512] {h,h}
    float2* red    = h_dup;  // alias: [8][16][32] reduction scratch (32KB)

    const int tid = threadIdx.x;
    const int cp  = tid & 31;   // col-pair within CTA slice
    const int kc  = tid >> 5;   // k-chunk (warp id)
    const int rank = blockIdx.x & (CLUSTER_SZ - 1);
    const int cl   = blockIdx.x / CLUSTER_SZ;
    const int b0   = cl * BC;
    const int c0   = rank * COLS_CTA;

    // One-time: Wrec slice -> SMEM, [cp][k] float2 layout (padded stride 514)
    for (int i = tid; i < 32 * 512; i += 256) {
        int k = i >> 5, c = i & 31;
        wrec_s[c * WSTRIDE2 + k] =
            *reinterpret_cast<const float2*>(Wrec + (size_t)k * H_ + c0 + 2 * c);
    }
    // init h_dup = {h0,h0} for all 16 batch rows
    {
        int b  = tid >> 4;
        int kb = (tid & 15) * 32;
        for (int j = 0; j < 32; j += 4) {
            float4 v = *reinterpret_cast<const float4*>(h0 + kb + j);
            float2* d = h_dup + b * 512 + kb + j;
            d[0] = make_float2(v.x, v.x);
            d[1] = make_float2(v.y, v.y);
            d[2] = make_float2(v.z, v.z);
            d[3] = make_float2(v.w, v.w);
        }
    }
    __syncthreads();

    // reduction-phase item ids: item = b*32 + cp
    const int rb0 = tid >> 5,          rcp0 = tid & 31;          // item tid
    const int rb1 = (tid + 256) >> 5,  rcp1 = tid & 31;          // item tid+256

    const float2* xp2  = reinterpret_cast<const float2*>(g_xproj);
    float2*       hall = reinterpret_cast<float2*>(g_hall);
    float2*       gh   = reinterpret_cast<float2*>(g_h);  // [2][256][256]

    const size_t hoff0 = (size_t)(b0 + rb0) * (H_ / 2) + (c0 >> 1) + rcp0;
    const size_t hoff1 = (size_t)(b0 + rb1) * (H_ / 2) + (c0 >> 1) + rcp1;

    for (int t = 0; t < T_; t++) {
        // prefetch xproj values used after the GEMM (hides DRAM latency)
        float2 xp0 = __ldg(&xp2[((size_t)(b0 + rb0) * T_ + t) * (H_ / 2) + (c0 >> 1) + rcp0]);
        float2 xp1 = __ldg(&xp2[((size_t)(b0 + rb1) * T_ + t) * (H_ / 2) + (c0 >> 1) + rcp1]);

        float2 acc[BC];
#pragma unroll
        for (int b = 0; b < BC; b++) acc[b] = make_float2(0.f, 0.f);

        const float2* wrow = wrec_s + cp * WSTRIDE2 + kc * 64;
        const float2* hrow = h_dup + kc * 64;
#pragma unroll 2
        for (int kk = 0; kk < 32; kk++) {
            float4 w = *reinterpret_cast<const float4*>(wrow + 2 * kk);
#pragma unroll
            for (int b = 0; b < BC; b++) {
                float4 hh = *reinterpret_cast<const float4*>(hrow + b * 512 + 2 * kk);
                acc[b] = ffma2(make_float2(hh.x, hh.y), make_float2(w.x, w.y), acc[b]);
                acc[b] = ffma2(make_float2(hh.z, hh.w), make_float2(w.z, w.w), acc[b]);
            }
        }
        __syncthreads();  // all reads of h_dup done; red aliases it
#pragma unroll
        for (int b = 0; b < BC; b++)
            red[(kc * 16 + b) * 32 + cp] = acc[b];
        __syncthreads();

        // reduce 8 k-chunk partials for items (rb0,rcp0) and (rb1,rcp1)
        float2 s0 = make_float2(0.f, 0.f), s1 = make_float2(0.f, 0.f);
#pragma unroll
        for (int k8 = 0; k8 < 8; k8++) {
            float2 a = red[(k8 * 16 + rb0) * 32 + rcp0];
            float2 c = red[(k8 * 16 + rb1) * 32 + rcp1];
            s0.x += a.x; s0.y += a.y;
            s1.x += c.x; s1.y += c.y;
        }
        float2 o0 = make_float2(tanhf(s0.x + xp0.x), tanhf(s0.y + xp0.y));
        float2 o1 = make_float2(tanhf(s1.x + xp1.x), tanhf(s1.y + xp1.y));

        hall[((size_t)(b0 + rb0) * T_ + t) * (H_ / 2) + (c0 >> 1) + rcp0] = o0;
        hall[((size_t)(b0 + rb1) * T_ + t) * (H_ / 2) + (c0 >> 1) + rcp1] = o1;

        const int w = (t + 1) & 1;
        const size_t gbase = (size_t)w * B_ * (H_ / 2);
        gh[gbase + hoff0] = o0;
        gh[gbase + hoff1] = o1;

        // cluster barrier: release our h slice, acquire peers' (flushes L1D)
        asm volatile("barrier.cluster.arrive.aligned;" ::: "memory");
        asm volatile("barrier.cluster.wait.aligned;"   ::: "memory");

        // rebuild duplicated h SMEM from the full 512-wide row in L2
        {
            int b  = tid >> 4;
            int kb = (tid & 15) * 32;
            const float4* src = reinterpret_cast<const float4*>(
                gh + gbase + (size_t)(b0 + b) * (H_ / 2)) + (kb >> 2);
            float2* dst = h_dup + b * 512 + kb;
#pragma unroll
            for (int j = 0; j < 8; j++) {
                float4 v = __ldcg(src + j);   // L2-direct
                dst[4 * j + 0] = make_float2(v.x, v.x);
                dst[4 * j + 1] = make_float2(v.y, v.y);
                dst[4 * j + 2] = make_float2(v.z, v.z);
                dst[4 * j + 3] = make_float2(v.w, v.w);
            }
        }
        __syncthreads();
    }
}

// ---------------------------------------------------------------------------
// Kernel C: out[r][d] = g_hall[r][:] @ Wout[:,d] + bout[d]
// ---------------------------------------------------------------------------
__global__ void __launch_bounds__(256, 1) rnn_outproj(
    const float* __restrict__ Wout,
    const float* __restrict__ bout,
    float* __restrict__ out)
{
    __shared__ __align__(16) float2 hd[64][64];  // {h,h} duplicated tile, 32KB
    const int tid = threadIdx.x;
    const int pair = tid & 31;
    const int rg = tid >> 5;
    const size_t r0 = (size_t)blockIdx.x * 64;

    float2 acc[8];
#pragma unroll
    for (int i = 0; i < 8; i++) acc[i] = make_float2(0.f, 0.f);

    const float2* __restrict__ Wo2 = reinterpret_cast<const float2*>(Wout);  // [k][32]

    for (int kc = 0; kc < H_; kc += 64) {
        __syncthreads();
        for (int i = tid; i < 64 * 64; i += 256) {
            int r = i >> 6, k = i & 63;
            float v = g_hall[(r0 + r) * H_ + kc + k];
            hd[r][k] = make_float2(v, v);
        }
        __syncthreads();

#pragma unroll 4
        for (int kk = 0; kk < 64; kk += 2) {
            float2 w0 = Wo2[(size_t)(kc + kk) * (DOUT / 2) + pair];
            float2 w1 = Wo2[(size_t)(kc + kk + 1) * (DOUT / 2) + pair];
#pragma unroll
            for (int i = 0; i < 8; i++) {
                int r = rg * 8 + i;
                float4 hx = *reinterpret_cast<const float4*>(&hd[r][kk]);
                acc[i] = ffma2(make_float2(hx.x, hx.y), w0, acc[i]);
                acc[i] = ffma2(make_float2(hx.z, hx.w), w1, acc[i]);
            }
        }
    }

    float2 bb = reinterpret_cast<const float2*>(bout)[pair];
    float2* __restrict__ out2 = reinterpret_cast<float2*>(out);
#pragma unroll
    for (int i = 0; i < 8; i++) {
        int r = rg * 8 + i;
        out2[(r0 + r) * (DOUT / 2) + pair] =
            make_float2(acc[i].x + bb.x, acc[i].y + bb.y);
    }
}

// ---------------------------------------------------------------------------
extern "C" void kernel_launch(void* const* d_in, const int* in_sizes, int n_in,
                              void* d_out, int out_size)
{
    const float* inputs = (const float*)d_in[0];
    const float* Win    = (const float*)d_in[1];
    const float* Wrec   = (const float*)d_in[2];
    const float* brec   = (const float*)d_in[3];
    const float* Wout   = (const float*)d_in[4];
    const float* bout   = (const float*)d_in[5];
    const float* h0     = (const float*)d_in[6];

    const int rec_smem = 131584 + 65536;  // Wrec slice + h_dup
    cudaFuncSetAttribute(rnn_recurrent,
                         cudaFuncAttributeMaxDynamicSharedMemorySize, rec_smem);

    rnn_xproj<<<(B_ * T_) / 16, 256>>>(inputs, Win, brec);
    rnn_recurrent<<<(B_ / BC) * CLUSTER_SZ, 256, rec_smem>>>(Wrec, h0);
    rnn_outproj<<<(B_ * T_) / 64, 256>>>(Wout, bout, (float*)d_out);
}